// round 10
// baseline (speedup 1.0000x reference)
#include <cuda_runtime.h>
#include <stdint.h>

#define NN       100000
#define NEMAX    1600000
#define IN_DIM   256
#define HID_DIM  128

// Scratch (allocation-free rule: __device__ globals, referenced DIRECTLY from
// kernels — no cudaGetSymbolAddress, no symbol-derived kernel arguments).
__device__ int   g_is64;                           // 1 if edge_index is int64
__device__ float g_dinv[NN];                       // rsqrt(weighted degree)
__device__ float g_deg[NN];                        // weighted degree accumulator
__device__ int   g_cnt[NN];                        // incoming-edge histogram
__device__ int   g_rowptr[NN + 1];                 // CSR row pointers (by dst)
__device__ int   g_cursor[NN];                     // fill cursors
__device__ int2  g_edge[NEMAX];                    // CSR: {src, norm-as-bits}
__device__ float g_tmp[(size_t)NN * HID_DIM];      // GEMM output (pre-agg)
__device__ float g_h[(size_t)NN * HID_DIM];        // layer-1 activations

// ---------------------------------------------------------------------------
// Edge-index dtype detection + safe accessors
// ---------------------------------------------------------------------------
// int64 node indices (< 100000, non-negative) have zero high words. Checking
// 8 odd-position int32 words == 0 identifies int64 vs int32 (P_false ~ 1e-40).
__global__ void k_detect(const int* __restrict__ ei32) {
    int is64 = 1;
    for (int i = 0; i < 8; i++)
        if (ei32[2 * i + 1] != 0) { is64 = 0; break; }
    g_is64 = is64;
}

__device__ __forceinline__ int edge_ld(const void* ei, size_t idx, int is64, int n) {
    int v = is64 ? (int)((const long long*)ei)[idx]
                 : ((const int*)ei)[idx];
    // clamp: any surprise degrades to wrong-but-measurable, not a crash
    return min(max(v, 0), n - 1);
}

// ---------------------------------------------------------------------------
// Normalization + CSR build
// ---------------------------------------------------------------------------
__global__ void k_init(int n) {
    int i = blockIdx.x * blockDim.x + threadIdx.x;
    if (i < n) { g_deg[i] = 1.0f; g_cnt[i] = 0; }   // self-loop weight = 1
}

// One pass over edges: weighted degree (float atomic) + histogram (int atomic)
__global__ void k_edge_pass(const void* __restrict__ ei,
                            const float* __restrict__ w, int E, int n) {
    int e = blockIdx.x * blockDim.x + threadIdx.x;
    if (e < E) {
        int is64 = g_is64;
        int d = edge_ld(ei, (size_t)E + e, is64, n);  // dst row of [2,E]
        atomicAdd(&g_deg[d], w[e]);
        atomicAdd(&g_cnt[d], 1);
    }
}

__global__ void k_dinv(int n) {
    int i = blockIdx.x * blockDim.x + threadIdx.x;
    if (i < n) g_dinv[i] = rsqrtf(g_deg[i]);        // deg >= 1 (self-loop)
}

// Single-block exclusive scan of g_cnt -> g_rowptr AND g_cursor.
__global__ void __launch_bounds__(1024) k_scan(int n) {
    __shared__ int part[1024];
    const int tid = threadIdx.x;
    const int per = (n + 1023) >> 10;
    const int s0 = tid * per;
    const int s1 = min(s0 + per, n);
    int s = 0;
    for (int i = s0; i < s1; i++) s += g_cnt[i];
    part[tid] = s;
    __syncthreads();
    for (int off = 1; off < 1024; off <<= 1) {
        int add = (tid >= off) ? part[tid - off] : 0;
        __syncthreads();
        part[tid] += add;
        __syncthreads();
    }
    int base = (tid == 0) ? 0 : part[tid - 1];
    for (int i = s0; i < s1; i++) {
        g_rowptr[i] = base;
        g_cursor[i] = base;
        base += g_cnt[i];
    }
    if (tid == 1023) g_rowptr[n] = part[1023];
}

// Scatter edges into CSR slots; precompute norm = dinv[src]*w*dinv[dst].
__global__ void k_fill(const void* __restrict__ ei,
                       const float* __restrict__ w, int E, int n) {
    int e = blockIdx.x * blockDim.x + threadIdx.x;
    if (e < E) {
        int is64 = g_is64;
        int s = edge_ld(ei, (size_t)e, is64, n);
        int d = edge_ld(ei, (size_t)E + e, is64, n);
        int pos = atomicAdd(&g_cursor[d], 1);
        float nv = g_dinv[s] * w[e] * g_dinv[d];
        g_edge[pos] = make_int2(s, __float_as_int(nv));
    }
}

// ---------------------------------------------------------------------------
// Tiled fp32 GEMM: g_tmp[M,128] = A[M,K] @ B[K,128]
// A = (A_GH ? g_h : Aparam). BM=128, BN=128, BK=8; 256 threads; 8x8 microtile.
// Software-pipelined: next K-tile prefetched into registers during compute.
// ---------------------------------------------------------------------------
template <int K, bool A_GH>
__global__ void __launch_bounds__(256)
k_gemm(const float* __restrict__ Aparam, const float* __restrict__ B, int M) {
    constexpr int BM = 128, BN = 128, BK = 8;
    __shared__ __align__(16) float As[BK][BM + 4];  // A transposed (m-major per k)
    __shared__ __align__(16) float Bs[BK][BN + 4];

    const float* __restrict__ A = A_GH ? (const float*)g_h : Aparam;

    const int tid = threadIdx.x;
    const int row0 = blockIdx.x * BM;
    const int tx = tid & 15;          // col group: cols tx*8 .. +7
    const int ty = tid >> 4;          // row group: rows ty*8 .. +7

    float acc[8][8];
#pragma unroll
    for (int i = 0; i < 8; i++)
#pragma unroll
        for (int j = 0; j < 8; j++) acc[i][j] = 0.0f;

    // A-tile: 128 rows x 8 k = 256 float4 (one per thread)
    const int a_row  = tid >> 1;            // 0..127
    const int a_col4 = (tid & 1) * 4;       // 0,4
    const int a_gr   = row0 + a_row;
    const bool a_ok  = (a_gr < M);
    const float* a_ptr = A + (size_t)a_gr * K + a_col4;
    // B-tile: 8 rows x 128 cols = 256 float4 (one per thread)
    const int b_row  = tid >> 5;            // 0..7
    const int b_col4 = (tid & 31) * 4;
    const float* b_ptr = B + (size_t)b_row * BN + b_col4;

    // Prologue: fetch tile 0 into registers
    float4 av = make_float4(0.f, 0.f, 0.f, 0.f);
    if (a_ok) av = *(const float4*)(a_ptr);
    float4 bv = *(const float4*)(b_ptr);

    for (int k0 = 0; k0 < K; k0 += BK) {
        // Commit prefetched tile to smem
        As[a_col4 + 0][a_row] = av.x;
        As[a_col4 + 1][a_row] = av.y;
        As[a_col4 + 2][a_row] = av.z;
        As[a_col4 + 3][a_row] = av.w;
        *(float4*)&Bs[b_row][b_col4] = bv;
        __syncthreads();

        // Prefetch next tile (overlaps with compute below)
        if (k0 + BK < K) {
            av = make_float4(0.f, 0.f, 0.f, 0.f);
            if (a_ok) av = *(const float4*)(a_ptr + k0 + BK);
            bv = *(const float4*)(b_ptr + (size_t)(k0 + BK) * BN);
        }

#pragma unroll
        for (int kk = 0; kk < BK; kk++) {
            float a[8], b[8];
            *(float4*)&a[0] = *(const float4*)&As[kk][ty * 8];
            *(float4*)&a[4] = *(const float4*)&As[kk][ty * 8 + 4];
            *(float4*)&b[0] = *(const float4*)&Bs[kk][tx * 8];
            *(float4*)&b[4] = *(const float4*)&Bs[kk][tx * 8 + 4];
#pragma unroll
            for (int i = 0; i < 8; i++)
#pragma unroll
                for (int j = 0; j < 8; j++) acc[i][j] += a[i] * b[j];
        }
        __syncthreads();
    }

#pragma unroll
    for (int i = 0; i < 8; i++) {
        int gr = row0 + ty * 8 + i;
        if (gr < M) {
            float* cp = g_tmp + (size_t)gr * BN + tx * 8;
            *(float4*)cp       = make_float4(acc[i][0], acc[i][1], acc[i][2], acc[i][3]);
            *(float4*)(cp + 4) = make_float4(acc[i][4], acc[i][5], acc[i][6], acc[i][7]);
        }
    }
}

// ---------------------------------------------------------------------------
// Gather-based SpMM over g_tmp, fused epilogue.
// One warp per destination node: 32 lanes x float4 = 128 features.
// LAYER1: writes relu(agg + bias) to g_h.  else: writes agg + bias to outp.
// ---------------------------------------------------------------------------
template <bool LAYER1>
__global__ void __launch_bounds__(256)
k_spmm(float* __restrict__ outp, const float* __restrict__ bias, int n) {
    const int node = (blockIdx.x * blockDim.x + threadIdx.x) >> 5;
    const int lane = threadIdx.x & 31;
    if (node >= n) return;

    const float* t = (const float*)g_tmp;
    float c = g_dinv[node];
    c *= c;
    float4 acc = ((const float4*)(t + (size_t)node * HID_DIM))[lane];
    acc.x *= c; acc.y *= c; acc.z *= c; acc.w *= c;

    const int beg = g_rowptr[node];
    const int end = g_rowptr[node + 1];
    int e = beg;
    // 4-way unroll: 4 independent random-row loads in flight (MLP=4)
    for (; e + 3 < end; e += 4) {
        int2 e0 = g_edge[e],     e1 = g_edge[e + 1];
        int2 e2 = g_edge[e + 2], e3 = g_edge[e + 3];
        float c0 = __int_as_float(e0.y), c1 = __int_as_float(e1.y);
        float c2 = __int_as_float(e2.y), c3 = __int_as_float(e3.y);
        float4 v0 = ((const float4*)(t + (size_t)e0.x * HID_DIM))[lane];
        float4 v1 = ((const float4*)(t + (size_t)e1.x * HID_DIM))[lane];
        float4 v2 = ((const float4*)(t + (size_t)e2.x * HID_DIM))[lane];
        float4 v3 = ((const float4*)(t + (size_t)e3.x * HID_DIM))[lane];
        acc.x += c0 * v0.x + c1 * v1.x + c2 * v2.x + c3 * v3.x;
        acc.y += c0 * v0.y + c1 * v1.y + c2 * v2.y + c3 * v3.y;
        acc.z += c0 * v0.z + c1 * v1.z + c2 * v2.z + c3 * v3.z;
        acc.w += c0 * v0.w + c1 * v1.w + c2 * v2.w + c3 * v3.w;
    }
    for (; e < end; e++) {
        int2 e0 = g_edge[e];
        float c0 = __int_as_float(e0.y);
        float4 v0 = ((const float4*)(t + (size_t)e0.x * HID_DIM))[lane];
        acc.x += c0 * v0.x; acc.y += c0 * v0.y;
        acc.z += c0 * v0.z; acc.w += c0 * v0.w;
    }

    float4 b = ((const float4*)bias)[lane];
    acc.x += b.x; acc.y += b.y; acc.z += b.z; acc.w += b.w;
    if (LAYER1) {
        acc.x = fmaxf(acc.x, 0.0f); acc.y = fmaxf(acc.y, 0.0f);
        acc.z = fmaxf(acc.z, 0.0f); acc.w = fmaxf(acc.w, 0.0f);
        ((float4*)((float*)g_h + (size_t)node * HID_DIM))[lane] = acc;
    } else {
        ((float4*)(outp + (size_t)node * HID_DIM))[lane] = acc;
    }
}

// ---------------------------------------------------------------------------
// kernel_launch — only harness-owned pointers cross the host/device boundary.
// ---------------------------------------------------------------------------
extern "C" void kernel_launch(void* const* d_in, const int* in_sizes, int n_in,
                              void* d_out, int out_size) {
    const float* x  = (const float*)d_in[0];
    const void*  ei = d_in[1];                 // int32 or int64 — detected on device
    const float* w  = (const float*)d_in[2];
    const float* W1 = (const float*)d_in[3];
    const float* b1 = (const float*)d_in[4];
    const float* W2 = (const float*)d_in[5];
    const float* b2 = (const float*)d_in[6];
    float*       out = (float*)d_out;

    const int n = in_sizes[0] / IN_DIM;   // 100000
    const int E = in_sizes[2];            // 1600000

    const int T = 256;
    const int nodeBlocks = (n + T - 1) / T;
    const int edgeBlocks = (E + T - 1) / T;
    const int spmmBlocks = (int)(((size_t)n * 32 + T - 1) / T);  // warp/node
    const int gemmBlocks = (n + 127) / 128;

    // --- dtype detection + normalization + CSR build ---
    k_detect<<<1, 1>>>((const int*)ei);
    k_init<<<nodeBlocks, T>>>(n);
    k_edge_pass<<<edgeBlocks, T>>>(ei, w, E, n);
    k_dinv<<<nodeBlocks, T>>>(n);
    k_scan<<<1, 1024>>>(n);
    k_fill<<<edgeBlocks, T>>>(ei, w, E, n);

    // --- layer 1: g_tmp = x @ W1 ; g_h = relu(Agg(g_tmp) + b1) ---
    k_gemm<IN_DIM, false><<<gemmBlocks, T>>>(x, W1, n);
    k_spmm<true><<<spmmBlocks, T>>>(nullptr, b1, n);

    // --- layer 2: g_tmp = g_h @ W2 ; out = Agg(g_tmp) + b2 ---
    k_gemm<HID_DIM, true><<<gemmBlocks, T>>>(nullptr, W2, n);
    k_spmm<false><<<spmmBlocks, T>>>(out, b2, n);
}